// round 2
// baseline (speedup 1.0000x reference)
#include <cuda_runtime.h>

// Regional Interaction Module — fully fused per-pixel kernel, v2.
// f_f[c] = s1*A[c] + s4*B[c] + v_r*(s2*Sa[c] + s3*Sb[c]) + fu_b[c]
// Composite coefficients computed once per block into smem (threads 0..51),
// then loaded register-resident as 13 x LDS.128 per thread.

#define HW       (512 * 512)
#define PLANE4   (HW / 4)          // 65536 float4 per plane
#define ITERS    4
#define THREADS  256

__device__ __forceinline__ float fast_sigmoid(float x) {
    // 1 / (1 + exp(-x)); EX2 + RCP path (2 MUFU). rel_err 1.4e-7 verified.
    return __fdividef(1.0f, 1.0f + __expf(-x));
}

template <bool TAIL>
__global__ void __launch_bounds__(THREADS, 3)
rim_kernel(const float* __restrict__ img, const float* __restrict__ mask,
           const float* __restrict__ qi_w, const float* __restrict__ qi_b,
           const float* __restrict__ ki_w, const float* __restrict__ ki_b,
           const float* __restrict__ vi_w, const float* __restrict__ vi_b,
           const float* __restrict__ qr_w, const float* __restrict__ qr_b,
           const float* __restrict__ kr_w, const float* __restrict__ kr_b,
           const float* __restrict__ vr_w, const float* __restrict__ vr_b,
           const float* __restrict__ fu_w, const float* __restrict__ fu_b,
           float* __restrict__ out, int n_q)
{
    // ---- per-block composite coefficient setup (parallel across 52 threads) ----
    __shared__ __align__(16) float coef[52];
    const int t = threadIdx.x;
    if (t < 52) {
        float v = 0.0f;
        if (t < 4) {
            v = (t < 3) ? qi_w[t] : qi_b[0];
        } else if (t < 8) {
            v = (t < 7) ? ki_w[t - 4] : ki_b[0];
        } else if (t < 12) {
            v = (t == 8) ? qr_w[0] : (t == 9) ? qr_b[0] : (t == 10) ? kr_w[0] : kr_b[0];
        } else if (t < 16) {
            v = (t == 12) ? vr_w[0] : (t == 13) ? vr_b[0] : 0.0f;
        } else if (t < 28) {                 // WA rows + bA in .w
            const int c = (t - 16) >> 2, i = (t - 16) & 3;
            const float a0 = fu_w[c * 6 + 0], a1 = fu_w[c * 6 + 1], a2 = fu_w[c * 6 + 2];
            if (i < 3) v = a0 * vi_w[0 * 3 + i] + a1 * vi_w[1 * 3 + i] + a2 * vi_w[2 * 3 + i];
            else       v = a0 * vi_b[0] + a1 * vi_b[1] + a2 * vi_b[2];
        } else if (t < 40) {                 // WB rows + bB in .w
            const int c = (t - 28) >> 2, i = (t - 28) & 3;
            const float b0 = fu_w[c * 6 + 3], b1 = fu_w[c * 6 + 4], b2 = fu_w[c * 6 + 5];
            if (i < 3) v = b0 * vi_w[0 * 3 + i] + b1 * vi_w[1 * 3 + i] + b2 * vi_w[2 * 3 + i];
            else       v = b0 * vi_b[0] + b1 * vi_b[1] + b2 * vi_b[2];
        } else if (t < 44) {                 // Sa
            const int c = t - 40;
            if (c < 3) v = fu_w[c * 6 + 0] + fu_w[c * 6 + 1] + fu_w[c * 6 + 2];
        } else if (t < 48) {                 // Sb
            const int c = t - 44;
            if (c < 3) v = fu_w[c * 6 + 3] + fu_w[c * 6 + 4] + fu_w[c * 6 + 5];
        } else {                             // fu_b
            const int c = t - 48;
            if (c < 3) v = fu_b[c];
        }
        coef[t] = v;
    }
    __syncthreads();

    // ---- load coefficients register-resident via LDS.128 ----
    const float4* c4 = reinterpret_cast<const float4*>(coef);
    const float4 cQ  = c4[0];   // qiw0..2, qib
    const float4 cK  = c4[1];   // kiw0..2, kib
    const float4 cR  = c4[2];   // qrw, qrb, krw, krb
    const float4 cV  = c4[3];   // vrw, vrb, -, -
    const float4 A0  = c4[4],  A1 = c4[5],  A2 = c4[6];   // WA rows (.w = bA)
    const float4 B0  = c4[7],  B1 = c4[8],  B2 = c4[9];   // WB rows (.w = bB)
    const float4 SA  = c4[10];  // Sa0..2
    const float4 SB  = c4[11];  // Sb0..2
    const float4 FB  = c4[12];  // fub0..2

    auto pixel = [&](float r, float g, float bl, float m,
                     float& o0, float& o1, float& o2) {
        const float qi = fmaf(cQ.z, bl, fmaf(cQ.y, g, fmaf(cQ.x, r, cQ.w)));
        const float ki = fmaf(cK.z, bl, fmaf(cK.y, g, fmaf(cK.x, r, cK.w)));
        const float qr = fmaf(cR.x, m, cR.y);
        const float kr = fmaf(cR.z, m, cR.w);
        const float vr = fmaf(cV.x, m, cV.y);
        const float s1 = fast_sigmoid(qi * ki);
        const float s2 = fast_sigmoid(qi * kr);
        const float s3 = fast_sigmoid(qr * kr);
        const float s4 = fast_sigmoid(qr * ki);
        const float p2 = vr * s2;
        const float p3 = vr * s3;

        float a, b2, f;
        a  = fmaf(A0.z, bl, fmaf(A0.y, g, fmaf(A0.x, r, A0.w)));
        b2 = fmaf(B0.z, bl, fmaf(B0.y, g, fmaf(B0.x, r, B0.w)));
        f  = fmaf(s1, a, FB.x); f = fmaf(s4, b2, f);
        f  = fmaf(p2, SA.x, f); f = fmaf(p3, SB.x, f);
        o0 = f;

        a  = fmaf(A1.z, bl, fmaf(A1.y, g, fmaf(A1.x, r, A1.w)));
        b2 = fmaf(B1.z, bl, fmaf(B1.y, g, fmaf(B1.x, r, B1.w)));
        f  = fmaf(s1, a, FB.y); f = fmaf(s4, b2, f);
        f  = fmaf(p2, SA.y, f); f = fmaf(p3, SB.y, f);
        o1 = f;

        a  = fmaf(A2.z, bl, fmaf(A2.y, g, fmaf(A2.x, r, A2.w)));
        b2 = fmaf(B2.z, bl, fmaf(B2.y, g, fmaf(B2.x, r, B2.w)));
        f  = fmaf(s1, a, FB.z); f = fmaf(s4, b2, f);
        f  = fmaf(p2, SA.z, f); f = fmaf(p3, SB.z, f);
        o2 = f;
    };

    const float4* img4  = reinterpret_cast<const float4*>(img);
    const float4* mask4 = reinterpret_cast<const float4*>(mask);
    float4*       out4  = reinterpret_cast<float4*>(out);

    const int tid    = blockIdx.x * THREADS + threadIdx.x;
    const int stride = gridDim.x * THREADS;

    #pragma unroll
    for (int k = 0; k < ITERS; k++) {
        const int q = tid + k * stride;
        if (TAIL) { if (q >= n_q) break; }
        const int b    = q >> 16;                 // q / PLANE4
        const int sq   = q & (PLANE4 - 1);
        const int base = b * (3 * PLANE4) + sq;

        const float4 R  = img4[base];
        const float4 G  = img4[base + PLANE4];
        const float4 Bc = img4[base + 2 * PLANE4];
        const float4 M  = mask4[q];

        float4 O0, O1, O2;
        pixel(R.x, G.x, Bc.x, M.x, O0.x, O1.x, O2.x);
        pixel(R.y, G.y, Bc.y, M.y, O0.y, O1.y, O2.y);
        pixel(R.z, G.z, Bc.z, M.z, O0.z, O1.z, O2.z);
        pixel(R.w, G.w, Bc.w, M.w, O0.w, O1.w, O2.w);

        out4[base]              = O0;
        out4[base + PLANE4]     = O1;
        out4[base + 2 * PLANE4] = O2;
    }
}

extern "C" void kernel_launch(void* const* d_in, const int* in_sizes, int n_in,
                              void* d_out, int out_size)
{
    const float* img  = (const float*)d_in[0];
    const float* mask = (const float*)d_in[1];
    const float* qi_w = (const float*)d_in[2];
    const float* qi_b = (const float*)d_in[3];
    const float* ki_w = (const float*)d_in[4];
    const float* ki_b = (const float*)d_in[5];
    const float* vi_w = (const float*)d_in[6];
    const float* vi_b = (const float*)d_in[7];
    const float* qr_w = (const float*)d_in[8];
    const float* qr_b = (const float*)d_in[9];
    const float* kr_w = (const float*)d_in[10];
    const float* kr_b = (const float*)d_in[11];
    const float* vr_w = (const float*)d_in[12];
    const float* vr_b = (const float*)d_in[13];
    const float* fu_w = (const float*)d_in[14];
    const float* fu_b = (const float*)d_in[15];

    const int n_pix = in_sizes[1];       // B*H*W
    const int n_q   = n_pix / 4;
    const int per_block = THREADS * ITERS;

    if (n_q % per_block == 0) {
        rim_kernel<false><<<n_q / per_block, THREADS>>>(
            img, mask, qi_w, qi_b, ki_w, ki_b, vi_w, vi_b,
            qr_w, qr_b, kr_w, kr_b, vr_w, vr_b, fu_w, fu_b,
            (float*)d_out, n_q);
    } else {
        rim_kernel<true><<<(n_q + per_block - 1) / per_block, THREADS>>>(
            img, mask, qi_w, qi_b, ki_w, ki_b, vi_w, vi_b,
            qr_w, qr_b, kr_w, kr_b, vr_w, vr_b, fu_w, fu_b,
            (float*)d_out, n_q);
    }
}

// round 3
// speedup vs baseline: 1.0972x; 1.0972x over previous
#include <cuda_runtime.h>

// Regional Interaction Module — v3.
// Scalar phase (register-resident 14 coefficients) computes s1,s4,p2,p3 per
// pixel; channel loop reloads each channel's 12 coefficients from smem via
// 3x LDS.128 (broadcast). launch_bounds(256,4) caps regs at 64 -> occ 50%.
// Streaming cache hints: img/out evict-first, mask default (may stay in L2
// across graph replays).

#define HW       (512 * 512)
#define PLANE4   (HW / 4)
#define ITERS    4
#define THREADS  256

__device__ __forceinline__ float fast_sigmoid(float x) {
    return __fdividef(1.0f, 1.0f + __expf(-x));
}

template <bool TAIL>
__global__ void __launch_bounds__(THREADS, 4)
rim_kernel(const float* __restrict__ img, const float* __restrict__ mask,
           const float* __restrict__ qi_w, const float* __restrict__ qi_b,
           const float* __restrict__ ki_w, const float* __restrict__ ki_b,
           const float* __restrict__ vi_w, const float* __restrict__ vi_b,
           const float* __restrict__ qr_w, const float* __restrict__ qr_b,
           const float* __restrict__ kr_w, const float* __restrict__ kr_b,
           const float* __restrict__ vr_w, const float* __restrict__ vr_b,
           const float* __restrict__ fu_w, const float* __restrict__ fu_b,
           float* __restrict__ out, int n_q)
{
    // ---- per-block composite coefficient setup ----
    // layout (float4 index):
    //  0: qiw0,qiw1,qiw2,qib   1: kiw0,kiw1,kiw2,kib
    //  2: qrw,qrb,krw,krb      3: vrw,vrb,0,0
    //  4..6:  WA row c (+bA in .w)
    //  7..9:  WB row c (+bB in .w)
    // 10..12: Sa[c],Sb[c],fub[c],0
    __shared__ __align__(16) float coef[52];
    const int t = threadIdx.x;
    if (t < 52) {
        float v = 0.0f;
        if (t < 4) {
            v = (t < 3) ? qi_w[t] : qi_b[0];
        } else if (t < 8) {
            v = (t < 7) ? ki_w[t - 4] : ki_b[0];
        } else if (t < 12) {
            v = (t == 8) ? qr_w[0] : (t == 9) ? qr_b[0] : (t == 10) ? kr_w[0] : kr_b[0];
        } else if (t < 16) {
            v = (t == 12) ? vr_w[0] : (t == 13) ? vr_b[0] : 0.0f;
        } else if (t < 28) {                 // WA rows + bA
            const int c = (t - 16) >> 2, i = (t - 16) & 3;
            const float a0 = fu_w[c * 6 + 0], a1 = fu_w[c * 6 + 1], a2 = fu_w[c * 6 + 2];
            if (i < 3) v = a0 * vi_w[0 * 3 + i] + a1 * vi_w[1 * 3 + i] + a2 * vi_w[2 * 3 + i];
            else       v = a0 * vi_b[0] + a1 * vi_b[1] + a2 * vi_b[2];
        } else if (t < 40) {                 // WB rows + bB
            const int c = (t - 28) >> 2, i = (t - 28) & 3;
            const float b0 = fu_w[c * 6 + 3], b1 = fu_w[c * 6 + 4], b2 = fu_w[c * 6 + 5];
            if (i < 3) v = b0 * vi_w[0 * 3 + i] + b1 * vi_w[1 * 3 + i] + b2 * vi_w[2 * 3 + i];
            else       v = b0 * vi_b[0] + b1 * vi_b[1] + b2 * vi_b[2];
        } else {                             // Sa, Sb, fub per channel
            const int c = (t - 40) >> 2, j = (t - 40) & 3;
            if (j == 0)      v = fu_w[c * 6 + 0] + fu_w[c * 6 + 1] + fu_w[c * 6 + 2];
            else if (j == 1) v = fu_w[c * 6 + 3] + fu_w[c * 6 + 4] + fu_w[c * 6 + 5];
            else if (j == 2) v = fu_b[c];
        }
        coef[t] = v;
    }
    __syncthreads();

    const float4* c4 = reinterpret_cast<const float4*>(coef);
    // persistent scalar-phase coefficients (14 live floats)
    const float4 cQ = c4[0];
    const float4 cK = c4[1];
    const float4 cR = c4[2];
    const float4 cV = c4[3];

    const float4* img4  = reinterpret_cast<const float4*>(img);
    const float4* mask4 = reinterpret_cast<const float4*>(mask);
    float4*       out4  = reinterpret_cast<float4*>(out);

    const int tid    = blockIdx.x * THREADS + threadIdx.x;
    const int stride = gridDim.x * THREADS;

    #pragma unroll
    for (int k = 0; k < ITERS; k++) {
        const int q = tid + k * stride;
        if (TAIL) { if (q >= n_q) break; }
        const int b    = q >> 16;
        const int sq   = q & (PLANE4 - 1);
        const int base = b * (3 * PLANE4) + sq;

        const float4 R  = __ldcs(&img4[base]);
        const float4 G  = __ldcs(&img4[base + PLANE4]);
        const float4 Bc = __ldcs(&img4[base + 2 * PLANE4]);
        const float4 M  = mask4[q];          // default policy: let mask linger in L2

        // ---- scalar phase: per-pixel gates ----
        float s1[4], s4v[4], p2[4], p3[4];
        {
            const float rr[4] = {R.x, R.y, R.z, R.w};
            const float gg[4] = {G.x, G.y, G.z, G.w};
            const float bb[4] = {Bc.x, Bc.y, Bc.z, Bc.w};
            const float mm[4] = {M.x, M.y, M.z, M.w};
            #pragma unroll
            for (int p = 0; p < 4; p++) {
                const float qi = fmaf(cQ.z, bb[p], fmaf(cQ.y, gg[p], fmaf(cQ.x, rr[p], cQ.w)));
                const float ki = fmaf(cK.z, bb[p], fmaf(cK.y, gg[p], fmaf(cK.x, rr[p], cK.w)));
                const float qr = fmaf(cR.x, mm[p], cR.y);
                const float kr = fmaf(cR.z, mm[p], cR.w);
                const float vr = fmaf(cV.x, mm[p], cV.y);
                s1[p]  = fast_sigmoid(qi * ki);
                s4v[p] = fast_sigmoid(qr * ki);
                p2[p]  = vr * fast_sigmoid(qi * kr);
                p3[p]  = vr * fast_sigmoid(qr * kr);
            }
        }

        // ---- channel loop: reload this channel's coefs from smem each time ----
        #pragma unroll
        for (int c = 0; c < 3; c++) {
            const float4 wa = c4[4 + c];     // LDS.128, broadcast
            const float4 wb = c4[7 + c];
            const float4 ws = c4[10 + c];    // Sa, Sb, fub

            float4 O;
            {
                const float rr[4] = {R.x, R.y, R.z, R.w};
                const float gg[4] = {G.x, G.y, G.z, G.w};
                const float bb[4] = {Bc.x, Bc.y, Bc.z, Bc.w};
                float oo[4];
                #pragma unroll
                for (int p = 0; p < 4; p++) {
                    const float A  = fmaf(wa.z, bb[p], fmaf(wa.y, gg[p], fmaf(wa.x, rr[p], wa.w)));
                    const float Bv = fmaf(wb.z, bb[p], fmaf(wb.y, gg[p], fmaf(wb.x, rr[p], wb.w)));
                    float f = fmaf(s1[p], A, ws.z);
                    f = fmaf(s4v[p], Bv, f);
                    f = fmaf(p2[p], ws.x, f);
                    f = fmaf(p3[p], ws.y, f);
                    oo[p] = f;
                }
                O.x = oo[0]; O.y = oo[1]; O.z = oo[2]; O.w = oo[3];
            }
            __stcs(&out4[base + c * PLANE4], O);   // evict-first store
        }
    }
}

extern "C" void kernel_launch(void* const* d_in, const int* in_sizes, int n_in,
                              void* d_out, int out_size)
{
    const float* img  = (const float*)d_in[0];
    const float* mask = (const float*)d_in[1];
    const float* qi_w = (const float*)d_in[2];
    const float* qi_b = (const float*)d_in[3];
    const float* ki_w = (const float*)d_in[4];
    const float* ki_b = (const float*)d_in[5];
    const float* vi_w = (const float*)d_in[6];
    const float* vi_b = (const float*)d_in[7];
    const float* qr_w = (const float*)d_in[8];
    const float* qr_b = (const float*)d_in[9];
    const float* kr_w = (const float*)d_in[10];
    const float* kr_b = (const float*)d_in[11];
    const float* vr_w = (const float*)d_in[12];
    const float* vr_b = (const float*)d_in[13];
    const float* fu_w = (const float*)d_in[14];
    const float* fu_b = (const float*)d_in[15];

    const int n_pix = in_sizes[1];       // B*H*W
    const int n_q   = n_pix / 4;
    const int per_block = THREADS * ITERS;

    if (n_q % per_block == 0) {
        rim_kernel<false><<<n_q / per_block, THREADS>>>(
            img, mask, qi_w, qi_b, ki_w, ki_b, vi_w, vi_b,
            qr_w, qr_b, kr_w, kr_b, vr_w, vr_b, fu_w, fu_b,
            (float*)d_out, n_q);
    } else {
        rim_kernel<true><<<(n_q + per_block - 1) / per_block, THREADS>>>(
            img, mask, qi_w, qi_b, ki_w, ki_b, vi_w, vi_b,
            qr_w, qr_b, kr_w, kr_b, vr_w, vr_b, fu_w, fu_b,
            (float*)d_out, n_q);
    }
}